// round 17
// baseline (speedup 1.0000x reference)
#include <cuda_runtime.h>
#include <cuda_fp16.h>
#include <cstdint>

#define BATCH 32
#define C 512
#define HW 3136
#define HID 128
#define PIX_TILE 128
#define TILES 25
#define PITCH 136           // smem row pitch in halves (272B)
#define EPS_BN 1e-5f

// Smem regions (halves): sH [128][PITCH], sW [128][PITCH], sB [64][PITCH]
#define SMEM_ELEMS ((HID + HID + 64) * PITCH)
// Natural need: 87040 B. Force 1 CTA/SM (R4 residency) by requesting 120 KB.
#define SMEM_ALLOC (120 * 1024)

__device__ __align__(16) __half g_w1[2*HID*C];
__device__ __align__(16) __half g_w2[2*C*HID];
__device__ float g_ss[2*2*HID];   // [br][{scale,shift}][HID]

__global__ void prep_kernel(const float* __restrict__ w1r, const float* __restrict__ w1i,
                            const float* __restrict__ w2r, const float* __restrict__ w2i,
                            const float* __restrict__ rmr, const float* __restrict__ rvr,
                            const float* __restrict__ gr,  const float* __restrict__ bbr,
                            const float* __restrict__ rmi, const float* __restrict__ rvi,
                            const float* __restrict__ gi,  const float* __restrict__ bbi)
{
    int idx = blockIdx.x * blockDim.x + threadIdx.x;
    if (idx < HID * C) {
        g_w1[idx]         = __float2half_rn(w1r[idx]);
        g_w1[HID*C + idx] = __float2half_rn(w1i[idx]);
        g_w2[idx]         = __float2half_rn(w2r[idx]);
        g_w2[C*HID + idx] = __float2half_rn(w2i[idx]);
    }
    if (idx < HID) {
        float s0 = gr[idx] / sqrtf(rvr[idx] + EPS_BN);
        g_ss[idx]         = s0;
        g_ss[HID + idx]   = bbr[idx] - rmr[idx] * s0;
        float s1 = gi[idx] / sqrtf(rvi[idx] + EPS_BN);
        g_ss[2*HID + idx] = s1;
        g_ss[3*HID + idx] = bbi[idx] - rmi[idx] * s1;
    }
}

__device__ __forceinline__ void ldsm4(uint32_t r[4], const __half* p) {
    uint32_t a = (uint32_t)__cvta_generic_to_shared(p);
    asm volatile("ldmatrix.sync.aligned.m8n8.x4.shared.b16 {%0,%1,%2,%3}, [%4];"
                 : "=r"(r[0]), "=r"(r[1]), "=r"(r[2]), "=r"(r[3]) : "r"(a));
}
__device__ __forceinline__ void ldsm4t(uint32_t r[4], const __half* p) {
    uint32_t a = (uint32_t)__cvta_generic_to_shared(p);
    asm volatile("ldmatrix.sync.aligned.m8n8.x4.trans.shared.b16 {%0,%1,%2,%3}, [%4];"
                 : "=r"(r[0]), "=r"(r[1]), "=r"(r[2]), "=r"(r[3]) : "r"(a));
}
__device__ __forceinline__ void mma_fp16(float d[4], const uint32_t a[4], uint32_t b0, uint32_t b1) {
    asm volatile("mma.sync.aligned.m16n8k16.row.col.f32.f16.f16.f32 "
                 "{%0,%1,%2,%3}, {%4,%5,%6,%7}, {%8,%9}, {%0,%1,%2,%3};"
                 : "+f"(d[0]), "+f"(d[1]), "+f"(d[2]), "+f"(d[3])
                 : "r"(a[0]), "r"(a[1]), "r"(a[2]), "r"(a[3]), "r"(b0), "r"(b1));
}

__global__ __launch_bounds__(256, 1)
void fused_kernel(const float* __restrict__ x, const int* __restrict__ mod,
                  float* __restrict__ out)
{
    extern __shared__ __half smem[];
    __half* sH = smem;
    __half* sW = sH + HID * PITCH;
    __half* sB = sW + HID * PITCH;

    const int tid  = threadIdx.x;
    const int warp = tid >> 5, lane = tid & 31;
    const int bimg = blockIdx.x / TILES;
    const int tile = blockIdx.x % TILES;
    const int p0   = tile * PIX_TILE;
    const int br   = (mod[bimg] == 1) ? 0 : 1;
    const int wr = warp >> 1, wc = warp & 1;          // 4x2 warp grid: 32 rows x 64 cols each
    const int g  = lane >> 2, tg = lane & 3;
    const int l16 = lane & 15, lh = lane >> 4;

    const float* xb = x   + (size_t)bimg * C * HW;
    float*       ob = out + (size_t)bimg * C * HW;
    const __half* w1 = g_w1 + br * HID * C;
    const __half* w2 = g_w2 + br * C * HID;

    float acc[2][8][4];
    #pragma unroll
    for (int a = 0; a < 2; a++)
        #pragma unroll
        for (int b2 = 0; b2 < 8; b2++)
            #pragma unroll
            for (int c2 = 0; c2 < 4; c2++) acc[a][b2][c2] = 0.f;

    // ============ Phase A: D1[128 hid][128 pix] = W1 . X, K=512 in 8 chunks of 64 ============
    for (int kc = 0; kc < C; kc += 64) {
        __syncthreads();
        // X chunk [64 ch][128 pix] fp32 -> fp16 in smem (R4 fill pattern)
        #pragma unroll
        for (int it = 0; it < 8; it++) {
            int idx = tid + it * 256;
            int row = idx >> 5;
            int pix = (idx & 31) << 2;
            float4 v = make_float4(0.f, 0.f, 0.f, 0.f);
            if (p0 + pix < HW)
                v = *(const float4*)(xb + (size_t)(kc + row) * HW + p0 + pix);
            *(__half2*)&sB[row*PITCH + pix]     = __floats2half2_rn(v.x, v.y);
            *(__half2*)&sB[row*PITCH + pix + 2] = __floats2half2_rn(v.z, v.w);
        }
        // W1 chunk: rows [0..128), cols [kc..kc+64)
        #pragma unroll
        for (int it = 0; it < 4; it++) {
            int idx = tid + it * 256;
            int row = idx >> 3;
            int c8  = (idx & 7) << 3;
            *(uint4*)&sW[row*PITCH + c8] = *(const uint4*)&w1[row*C + kc + c8];
        }
        __syncthreads();
        #pragma unroll
        for (int ks = 0; ks < 64; ks += 16) {
            uint32_t A[2][4];
            #pragma unroll
            for (int mf = 0; mf < 2; mf++) {
                const int ro = (32*wr + 16*mf + l16) * PITCH + ks + 8*lh;
                ldsm4(A[mf], &sW[ro]);
            }
            uint32_t Bt[4][4];
            #pragma unroll
            for (int nf = 0; nf < 4; nf++) {
                const int bo = (ks + l16) * PITCH + 64*wc + 16*nf + 8*lh;
                ldsm4t(Bt[nf], &sB[bo]);
            }
            #pragma unroll
            for (int mf = 0; mf < 2; mf++)
                #pragma unroll
                for (int nf = 0; nf < 4; nf++)
                    #pragma unroll
                    for (int hhalf = 0; hhalf < 2; hhalf++)
                        mma_fp16(acc[mf][nf*2 + hhalf], A[mf],
                                 Bt[nf][2*hhalf], Bt[nf][2*hhalf+1]);
        }
    }

    // Epilogue A: BN scale/shift + ReLU -> fp16 h in sH
    __syncthreads();
    #pragma unroll
    for (int mf = 0; mf < 2; mf++) {
        #pragma unroll
        for (int rh = 0; rh < 2; rh++) {
            int row = 32*wr + 16*mf + 8*rh + g;
            float sc = g_ss[br*2*HID + row];
            float sh = g_ss[br*2*HID + HID + row];
            #pragma unroll
            for (int n8 = 0; n8 < 8; n8++) {
                int col = 64*wc + 8*n8 + 2*tg;
                float v0 = fmaxf(fmaf(acc[mf][n8][2*rh+0], sc, sh), 0.f);
                float v1 = fmaxf(fmaf(acc[mf][n8][2*rh+1], sc, sh), 0.f);
                *(__half2*)&sH[row*PITCH + col] = __floats2half2_rn(v0, v1);
            }
        }
    }
    __syncthreads();

    // ============ Phase B: out[512 c][128 pix] = W2 . h, K=128, 4 chunks of 128 c ============
    for (int cc = 0; cc < C; cc += 128) {
        __syncthreads();   // prior mma reads of sW done before overwrite
        #pragma unroll
        for (int it = 0; it < 8; it++) {
            int idx = tid + it * 256;
            int row = idx >> 4;
            int c8  = (idx & 15) << 3;
            *(uint4*)&sW[row*PITCH + c8] = *(const uint4*)&w2[(cc + row)*HID + c8];
        }
        __syncthreads();
        #pragma unroll
        for (int a = 0; a < 2; a++)
            #pragma unroll
            for (int b2 = 0; b2 < 8; b2++)
                #pragma unroll
                for (int c2 = 0; c2 < 4; c2++) acc[a][b2][c2] = 0.f;

        #pragma unroll
        for (int ks = 0; ks < 128; ks += 16) {
            uint32_t A[2][4];
            #pragma unroll
            for (int mf = 0; mf < 2; mf++) {
                const int ro = (32*wr + 16*mf + l16) * PITCH + ks + 8*lh;
                ldsm4(A[mf], &sW[ro]);
            }
            uint32_t Bt[4][4];
            #pragma unroll
            for (int nf = 0; nf < 4; nf++) {
                const int bo = (ks + l16) * PITCH + 64*wc + 16*nf + 8*lh;
                ldsm4t(Bt[nf], &sH[bo]);
            }
            #pragma unroll
            for (int mf = 0; mf < 2; mf++)
                #pragma unroll
                for (int nf = 0; nf < 4; nf++)
                    #pragma unroll
                    for (int hhalf = 0; hhalf < 2; hhalf++)
                        mma_fp16(acc[mf][nf*2 + hhalf], A[mf],
                                 Bt[nf][2*hhalf], Bt[nf][2*hhalf+1]);
        }
        // Epilogue B: fp32 store (paired cols -> float2)
        #pragma unroll
        for (int mf = 0; mf < 2; mf++)
            #pragma unroll
            for (int rh = 0; rh < 2; rh++) {
                int row = 32*wr + 16*mf + 8*rh + g;
                #pragma unroll
                for (int n8 = 0; n8 < 8; n8++) {
                    int col = 64*wc + 8*n8 + 2*tg;
                    if (p0 + col < HW) {
                        float2 v = make_float2(acc[mf][n8][2*rh], acc[mf][n8][2*rh+1]);
                        *(float2*)&ob[(size_t)(cc + row) * HW + p0 + col] = v;
                    }
                }
            }
    }
}

extern "C" void kernel_launch(void* const* d_in, const int* in_sizes, int n_in,
                              void* d_out, int out_size)
{
    (void)in_sizes; (void)n_in; (void)out_size;
    const float* x   = (const float*)d_in[0];
    const int*   md  = (const int*)  d_in[1];
    const float* w1r = (const float*)d_in[2];
    const float* rmr = (const float*)d_in[3];
    const float* rvr = (const float*)d_in[4];
    const float* gr  = (const float*)d_in[5];
    const float* bbr = (const float*)d_in[6];
    const float* w2r = (const float*)d_in[7];
    const float* w1i = (const float*)d_in[8];
    const float* rmi = (const float*)d_in[9];
    const float* rvi = (const float*)d_in[10];
    const float* gi  = (const float*)d_in[11];
    const float* bbi = (const float*)d_in[12];
    const float* w2i = (const float*)d_in[13];
    float* out = (float*)d_out;

    cudaFuncSetAttribute(fused_kernel, cudaFuncAttributeMaxDynamicSharedMemorySize, SMEM_ALLOC);

    prep_kernel<<<(HID * C + 255) / 256, 256>>>(w1r, w1i, w2r, w2i,
                                                rmr, rvr, gr, bbr,
                                                rmi, rvi, gi, bbi);
    fused_kernel<<<BATCH * TILES, 256, SMEM_ALLOC>>>(x, md, out);
}